// round 3
// baseline (speedup 1.0000x reference)
#include <cuda_runtime.h>

// ---------------------------------------------------------------------------
// HourlyWaterQualityPredictor — fused ConvLSTM(12 steps) + decoder, fp32.
// R3: 1024 threads/CTA (8 warps/SMSP) for latency hiding. Gates split across
// thread pairs: g=0 accumulates I,F; g=1 accumulates O,G and owns c-state.
// One CTA = NB=8 batches, 128 threads per batch.
// Thread (bi, g, hp, r): batch bi, gate-half g, hidden pair {2hp,2hp+1}, row r.
// Conv weights in smem permuted as [k(9)][ic(35)][oc(128)].
// ---------------------------------------------------------------------------

#define NB    8
#define NTHR  1024
#define ICH   35              // 3 input + 32 hidden channels
#define INS   592             // per-batch floats: 35*16 + 32 (hour feature)
#define WCNT  (9 * 35 * 128)  // 40320 conv weights
#define SCR_F (NB * 64 * 9 * 2)  // scratch: NB*64 slots * 9 ull (padded) in floats

typedef unsigned long long ull;

__device__ __forceinline__ ull fma2(ull a, ull b, ull c) {
    ull d;
    asm("fma.rn.f32x2 %0, %1, %2, %3;" : "=l"(d) : "l"(a), "l"(b), "l"(c));
    return d;
}
__device__ __forceinline__ ull bcast2(float v) {
    ull d;
    asm("mov.b64 %0, {%1, %1};" : "=l"(d) : "f"(v));
    return d;
}
__device__ __forceinline__ ull pack2(float a, float b) {
    ull d;
    asm("mov.b64 %0, {%1, %2};" : "=l"(d) : "f"(a), "f"(b));
    return d;
}
__device__ __forceinline__ float2 unpack2(ull v) {
    float2 r;
    asm("mov.b64 {%0, %1}, %2;" : "=f"(r.x), "=f"(r.y) : "l"(v));
    return r;
}

__device__ __forceinline__ float sigf(float v) {
    return __fdividef(1.0f, 1.0f + __expf(-v));
}
__device__ __forceinline__ float tanh_fast(float v) {
    v = fminf(fmaxf(v, -15.0f), 15.0f);
    float e = __expf(2.0f * v);
    return __fdividef(e - 1.0f, e + 1.0f);
}

extern __shared__ float smem[];

__global__ __launch_bounds__(NTHR, 1)
void wq_fused_kernel(const float* __restrict__ x,      const float* __restrict__ hour,
                     const float* __restrict__ conv_w, const float* __restrict__ conv_b,
                     const float* __restrict__ he_w1,  const float* __restrict__ he_b1,
                     const float* __restrict__ he_w2,  const float* __restrict__ he_b2,
                     const float* __restrict__ d_w1,   const float* __restrict__ d_b1,
                     const float* __restrict__ d_w2,   const float* __restrict__ d_b2,
                     const float* __restrict__ d_w3,   const float* __restrict__ d_b3,
                     float* __restrict__ out, int B)
{
    float* w_s    = smem;             // [9][35][128]
    float* b_s    = w_s + WCNT;       // [128]
    float* in_all = b_s + 128;        // [NB][INS]
    ull*   scrU   = (ull*)(in_all + NB * INS);  // [NB*64][9] ull (8B-aligned)

    const int tid = threadIdx.x;
    const int bi  = tid >> 7;         // batch within CTA (0..7)
    const int tib = tid & 127;        // thread within batch
    const int g   = tib >> 6;         // gate half: 0 -> I,F ; 1 -> O,G
    const int hp  = (tib >> 2) & 15;  // hidden-channel pair 0..15
    const int r   = tib & 3;          // image row 0..3
    const int b0  = blockIdx.x * NB;
    const int b   = b0 + bi;
    const bool valid = (b < B);
    const int  bld   = valid ? b : (B - 1);

    // ---- stage conv weights into smem, permuted [k][ic][oc] ----
    for (int s = tid; s < WCNT; s += NTHR) {
        int oc  = s / 315;
        int rem = s - oc * 315;
        int ic  = rem / 9;
        int k   = rem - ic * 9;
        w_s[(k * 35 + ic) * 128 + oc] = conv_w[s];
    }
    for (int s = tid; s < 128; s += NTHR) b_s[s] = conv_b[s];

    // ---- zero state, then load x_0 ----
    for (int s = tid; s < NB * INS; s += NTHR) in_all[s] = 0.0f;
    __syncthreads();
    for (int s = tid; s < NB * 48; s += NTHR) {
        int bb = s / 48, cp = s - bb * 48;
        int gb = b0 + bb;
        if (gb < B) in_all[bb * INS + cp] = x[gb * 576 + cp];
    }
    __syncthreads();

    float* inb = in_all + bi * INS;
    const int gA = g * 64;       // gate A offset: I (0) or O (64)
    const int gB = g * 64 + 32;  // gate B offset: F (32) or G (96)
    const float* wb0 = w_s + 2 * hp;

    ull cst2[4];                 // packed c-state (only meaningful for g==1)
    #pragma unroll
    for (int p = 0; p < 4; p++) cst2[p] = 0ULL;

    ull* scme = scrU + (((bi << 6) + (hp << 2) + r) * 9);

    // ---------------------- 12-step ConvLSTM recurrence ----------------------
    #pragma unroll 1
    for (int t = 0; t < 12; ++t) {
        const ull bA2 = *reinterpret_cast<const ull*>(b_s + gA + 2 * hp);
        const ull bB2 = *reinterpret_cast<const ull*>(b_s + gB + 2 * hp);
        ull aA[4], aB[4];
        #pragma unroll
        for (int p = 0; p < 4; p++) { aA[p] = bA2; aB[p] = bB2; }

        #pragma unroll 1
        for (int ic = 0; ic < ICH; ++ic) {
            const float* rowbase = inb + ic * 16;
            float4 vm = make_float4(0.f, 0.f, 0.f, 0.f);
            float4 vp = make_float4(0.f, 0.f, 0.f, 0.f);
            if (r > 0) vm = *reinterpret_cast<const float4*>(rowbase + (r - 1) * 4);
            float4 v0 = *reinterpret_cast<const float4*>(rowbase + r * 4);
            if (r < 3) vp = *reinterpret_cast<const float4*>(rowbase + (r + 1) * 4);

            ull vvm[4], vv0[4], vvp[4];
            vvm[0] = bcast2(vm.x); vvm[1] = bcast2(vm.y); vvm[2] = bcast2(vm.z); vvm[3] = bcast2(vm.w);
            vv0[0] = bcast2(v0.x); vv0[1] = bcast2(v0.y); vv0[2] = bcast2(v0.z); vv0[3] = bcast2(v0.w);
            vvp[0] = bcast2(vp.x); vvp[1] = bcast2(vp.y); vvp[2] = bcast2(vp.z); vvp[3] = bcast2(vp.w);

            const float* wic = wb0 + ic * 128;
            #pragma unroll
            for (int k = 0; k < 9; ++k) {
                const int dy = k / 3 - 1;
                const int dx = (k % 3) - 1;
                const float* wp2 = wic + k * 4480;   // k*(35*128)
                ull wA2 = *reinterpret_cast<const ull*>(wp2 + gA);
                ull wB2 = *reinterpret_cast<const ull*>(wp2 + gB);
                #pragma unroll
                for (int p = 0; p < 4; ++p) {
                    const int sx = p + dx;
                    if (sx >= 0 && sx < 4) {
                        ull vv = (dy == -1) ? vvm[sx] : ((dy == 0) ? vv0[sx] : vvp[sx]);
                        aA[p] = fma2(wA2, vv, aA[p]);
                        aB[p] = fma2(wB2, vv, aB[p]);
                    }
                }
            }
        }

        // g=0: publish sigmoid(I), sigmoid(F) through scratch
        if (g == 0) {
            #pragma unroll
            for (int p = 0; p < 4; p++) {
                float2 vi = unpack2(aA[p]);
                float2 vf = unpack2(aB[p]);
                scme[p]     = pack2(sigf(vi.x), sigf(vi.y));
                scme[4 + p] = pack2(sigf(vf.x), sigf(vf.y));
            }
        }
        __syncthreads();   // conv reads done + scratch visible

        // g=1: complete the cell, write h
        if (g == 1) {
            #pragma unroll
            for (int p = 0; p < 4; p++) {
                float2 vo = unpack2(aA[p]);
                float2 vg = unpack2(aB[p]);
                float2 si = unpack2(scme[p]);
                float2 sf = unpack2(scme[4 + p]);
                float2 cp = unpack2(cst2[p]);
                float c0 = sf.x * cp.x + si.x * tanh_fast(vg.x);
                float c1 = sf.y * cp.y + si.y * tanh_fast(vg.y);
                cst2[p] = pack2(c0, c1);
                inb[(3 + 2 * hp) * 16 + r * 4 + p] = sigf(vo.x) * tanh_fast(c0);
                inb[(4 + 2 * hp) * 16 + r * 4 + p] = sigf(vo.y) * tanh_fast(c1);
            }
        }

        if (t < 11) {
            for (int s = tid; s < NB * 48; s += NTHR) {
                int bb = s / 48, cp = s - bb * 48;
                int gb = b0 + bb;
                if (gb < B) in_all[bb * INS + cp] = x[gb * 576 + (t + 1) * 48 + cp];
            }
        }
        __syncthreads();
    }

    // ------------------------------ decoder ------------------------------
    // hour embedding -> z[512..543] stored at inb[560..591] (z[i] = inb[48+i])
    if (tib < 32) {
        float hv  = hour[bld];
        float acc = he_b2[tib];
        #pragma unroll
        for (int k2 = 0; k2 < 16; ++k2) {
            float tt = fmaxf(hv * he_w1[k2] + he_b1[k2], 0.0f);
            acc += tt * he_w2[k2 * 32 + tib];
        }
        inb[560 + tib] = acc;
    }
    __syncthreads();

    // L1: 544 -> 256, each thread computes 2 outputs
    float a1x, a1y;
    {
        const int j0 = tib * 2;
        a1x = d_b1[j0]; a1y = d_b1[j0 + 1];
        const float* zz = inb + 48;
        #pragma unroll 4
        for (int i = 0; i < 544; ++i) {
            float zi = zz[i];
            float2 w = *reinterpret_cast<const float2*>(d_w1 + i * 256 + j0);
            a1x += zi * w.x; a1y += zi * w.y;
        }
        a1x = fmaxf(a1x, 0.0f); a1y = fmaxf(a1y, 0.0f);
    }
    __syncthreads();   // all z reads done
    {
        const int j0 = tib * 2;
        inb[j0] = a1x; inb[j0 + 1] = a1y;
    }
    __syncthreads();

    // L2: 256 -> 128, each thread computes 1 output; writes to [256..384)
    {
        float a2 = d_b2[tib];
        #pragma unroll 4
        for (int i = 0; i < 256; ++i)
            a2 += inb[i] * d_w2[i * 128 + tib];
        inb[256 + tib] = fmaxf(a2, 0.0f);   // disjoint from read region [0..256)
    }
    __syncthreads();

    // L3: 128 -> 30 + sigmoid
    if (tib < 30 && valid) {
        float a3 = d_b3[tib];
        #pragma unroll 4
        for (int i = 0; i < 128; ++i)
            a3 += inb[256 + i] * d_w3[i * 30 + tib];
        out[b * 30 + tib] = sigf(a3);
    }
}

extern "C" void kernel_launch(void* const* d_in, const int* in_sizes, int n_in,
                              void* d_out, int out_size)
{
    const float* x      = (const float*)d_in[0];
    const float* hour   = (const float*)d_in[1];
    const float* conv_w = (const float*)d_in[2];
    const float* conv_b = (const float*)d_in[3];
    const float* he_w1  = (const float*)d_in[4];
    const float* he_b1  = (const float*)d_in[5];
    const float* he_w2  = (const float*)d_in[6];
    const float* he_b2  = (const float*)d_in[7];
    const float* d_w1   = (const float*)d_in[8];
    const float* d_b1   = (const float*)d_in[9];
    const float* d_w2   = (const float*)d_in[10];
    const float* d_b2   = (const float*)d_in[11];
    const float* d_w3   = (const float*)d_in[12];
    const float* d_b3   = (const float*)d_in[13];

    const int B    = in_sizes[0] / 576;          // 12*3*4*4
    const int grid = (B + NB - 1) / NB;
    // floats: weights 40320 + bias 128 + in_all 4736 ; ull scratch 4608
    const size_t sm = (size_t)(WCNT + 128 + NB * INS) * sizeof(float)
                    + (size_t)(NB * 64 * 9) * sizeof(ull);   // 217,600 B

    cudaFuncSetAttribute(wq_fused_kernel,
                         cudaFuncAttributeMaxDynamicSharedMemorySize, (int)sm);

    wq_fused_kernel<<<grid, NTHR, sm>>>(x, hour, conv_w, conv_b,
                                        he_w1, he_b1, he_w2, he_b2,
                                        d_w1, d_b1, d_w2, d_b2, d_w3, d_b3,
                                        (float*)d_out, B);
}

// round 4
// speedup vs baseline: 1.0991x; 1.0991x over previous
#include <cuda_runtime.h>

// ---------------------------------------------------------------------------
// HourlyWaterQualityPredictor — fused ConvLSTM(12 steps) + decoder, fp32.
// R4: NB=16 batches/CTA, 512 threads; each thread accumulates 2 batches
// (bi8, bi8+8) so each weight LDS feeds 2x the FFMA2 work (ratio 5.7:1).
// Thread (bi8, hp, r): hidden pair {2hp,2hp+1}, row r, batches bi8 & bi8+8.
// Conv weights in smem permuted [k(9)][ic(35)][oc(128)]; decoder scratch
// reuses the weight region after the recurrence.
// ---------------------------------------------------------------------------

#define NB    16
#define NTHR  512
#define ICH   35
#define INS   560             // per-batch floats: 35*16
#define WCNT  (9 * 35 * 128)  // 40320

typedef unsigned long long ull;

__device__ __forceinline__ ull fma2(ull a, ull b, ull c) {
    ull d;
    asm("fma.rn.f32x2 %0, %1, %2, %3;" : "=l"(d) : "l"(a), "l"(b), "l"(c));
    return d;
}
__device__ __forceinline__ ull bcast2(float v) {
    ull d;
    asm("mov.b64 %0, {%1, %1};" : "=l"(d) : "f"(v));
    return d;
}
__device__ __forceinline__ ull pack2(float a, float b) {
    ull d;
    asm("mov.b64 %0, {%1, %2};" : "=l"(d) : "f"(a), "f"(b));
    return d;
}
__device__ __forceinline__ float2 unpack2(ull v) {
    float2 r;
    asm("mov.b64 {%0, %1}, %2;" : "=f"(r.x), "=f"(r.y) : "l"(v));
    return r;
}

__device__ __forceinline__ float sigf(float v) {
    return __fdividef(1.0f, 1.0f + __expf(-v));
}
__device__ __forceinline__ float tanh_fast(float v) {
    v = fminf(fmaxf(v, -15.0f), 15.0f);
    float e = __expf(2.0f * v);
    return __fdividef(e - 1.0f, e + 1.0f);
}

#define GETC(v4, idx) ((idx) == 0 ? (v4).x : (idx) == 1 ? (v4).y : (idx) == 2 ? (v4).z : (v4).w)

extern __shared__ float smem[];

__global__ __launch_bounds__(NTHR, 1)
void wq_fused_kernel(const float* __restrict__ x,      const float* __restrict__ hour,
                     const float* __restrict__ conv_w, const float* __restrict__ conv_b,
                     const float* __restrict__ he_w1,  const float* __restrict__ he_b1,
                     const float* __restrict__ he_w2,  const float* __restrict__ he_b2,
                     const float* __restrict__ d_w1,   const float* __restrict__ d_b1,
                     const float* __restrict__ d_w2,   const float* __restrict__ d_b2,
                     const float* __restrict__ d_w3,   const float* __restrict__ d_b3,
                     float* __restrict__ out, int B)
{
    float* w_s    = smem;             // [9][35][128]; decoder scratch later
    float* b_s    = w_s + WCNT;       // [128]
    float* in_all = b_s + 128;        // [NB][INS]
    float* hf_s   = in_all + NB * INS;// [NB][32]

    const int tid = threadIdx.x;
    const int bi8 = tid >> 6;         // 0..7 -> batches bi8, bi8+8
    const int tib = tid & 63;
    const int hp  = tib >> 2;         // hidden pair 0..15
    const int r   = tib & 3;          // image row
    const int b0  = blockIdx.x * NB;

    // ---- stage conv weights, permuted [k][ic][oc] ----
    for (int s = tid; s < WCNT; s += NTHR) {
        int oc  = s / 315;
        int rem = s - oc * 315;
        int ic  = rem / 9;
        int k   = rem - ic * 9;
        w_s[(k * 35 + ic) * 128 + oc] = conv_w[s];
    }
    for (int s = tid; s < 128; s += NTHR) b_s[s] = conv_b[s];

    // ---- zero state, load x_0 (as float4: 16 batches x 12 vec4) ----
    for (int s = tid; s < NB * INS; s += NTHR) in_all[s] = 0.0f;
    __syncthreads();
    if (tid < NB * 12) {
        int bb = tid / 12, q = tid - bb * 12;
        int gb = b0 + bb;
        if (gb < B)
            *reinterpret_cast<float4*>(in_all + bb * INS + q * 4) =
                *reinterpret_cast<const float4*>(x + (size_t)gb * 576 + q * 4);
    }
    __syncthreads();

    float* inA = in_all + bi8 * INS;
    float* inB = in_all + (bi8 + 8) * INS;
    const float* wb0 = w_s + 2 * hp;

    ull cstA[4], cstB[4];
    #pragma unroll
    for (int p = 0; p < 4; p++) { cstA[p] = 0ULL; cstB[p] = 0ULL; }

    // ---------------------- 12-step ConvLSTM recurrence ----------------------
    #pragma unroll 1
    for (int t = 0; t < 12; ++t) {
        ull acc[2][4][4];   // [batch][gate][px], each = 2 oc packed
        {
            ull bI = *reinterpret_cast<const ull*>(b_s +      2 * hp);
            ull bF = *reinterpret_cast<const ull*>(b_s + 32 + 2 * hp);
            ull bO = *reinterpret_cast<const ull*>(b_s + 64 + 2 * hp);
            ull bG = *reinterpret_cast<const ull*>(b_s + 96 + 2 * hp);
            #pragma unroll
            for (int p = 0; p < 4; p++) {
                acc[0][0][p] = bI; acc[1][0][p] = bI;
                acc[0][1][p] = bF; acc[1][1][p] = bF;
                acc[0][2][p] = bO; acc[1][2][p] = bO;
                acc[0][3][p] = bG; acc[1][3][p] = bG;
            }
        }

        #pragma unroll 1
        for (int ic = 0; ic < ICH; ++ic) {
            const float* rA = inA + ic * 16;
            const float* rB = inB + ic * 16;
            float4 amA = make_float4(0.f,0.f,0.f,0.f), apA = amA;
            float4 amB = amA, apB = amA;
            if (r > 0) { amA = *reinterpret_cast<const float4*>(rA + (r-1)*4);
                         amB = *reinterpret_cast<const float4*>(rB + (r-1)*4); }
            float4 a0A = *reinterpret_cast<const float4*>(rA + r*4);
            float4 a0B = *reinterpret_cast<const float4*>(rB + r*4);
            if (r < 3) { apA = *reinterpret_cast<const float4*>(rA + (r+1)*4);
                         apB = *reinterpret_cast<const float4*>(rB + (r+1)*4); }

            const float* wic = wb0 + ic * 128;
            #pragma unroll
            for (int k = 0; k < 9; ++k) {
                const int dy = k / 3 - 1;
                const int dx = (k % 3) - 1;
                const float* wp2 = wic + k * 4480;
                ull w0 = *reinterpret_cast<const ull*>(wp2);
                ull w1 = *reinterpret_cast<const ull*>(wp2 + 32);
                ull w2 = *reinterpret_cast<const ull*>(wp2 + 64);
                ull w3 = *reinterpret_cast<const ull*>(wp2 + 96);
                #pragma unroll
                for (int p = 0; p < 4; ++p) {
                    const int sx = p + dx;
                    if (sx >= 0 && sx < 4) {
                        float4 rwA = (dy == -1) ? amA : ((dy == 0) ? a0A : apA);
                        float4 rwB = (dy == -1) ? amB : ((dy == 0) ? a0B : apB);
                        ull ua = bcast2(GETC(rwA, sx));
                        ull ub = bcast2(GETC(rwB, sx));
                        acc[0][0][p] = fma2(w0, ua, acc[0][0][p]);
                        acc[1][0][p] = fma2(w0, ub, acc[1][0][p]);
                        acc[0][1][p] = fma2(w1, ua, acc[0][1][p]);
                        acc[1][1][p] = fma2(w1, ub, acc[1][1][p]);
                        acc[0][2][p] = fma2(w2, ua, acc[0][2][p]);
                        acc[1][2][p] = fma2(w2, ub, acc[1][2][p]);
                        acc[0][3][p] = fma2(w3, ua, acc[0][3][p]);
                        acc[1][3][p] = fma2(w3, ub, acc[1][3][p]);
                    }
                }
            }
        }

        // LSTM cell update (registers only), both batches
        float hA[2][4], hB[2][4];
        #pragma unroll
        for (int p = 0; p < 4; p++) {
            float2 vi = unpack2(acc[0][0][p]);
            float2 vf = unpack2(acc[0][1][p]);
            float2 vo = unpack2(acc[0][2][p]);
            float2 vg = unpack2(acc[0][3][p]);
            float2 cp = unpack2(cstA[p]);
            float c0 = sigf(vf.x) * cp.x + sigf(vi.x) * tanh_fast(vg.x);
            float c1 = sigf(vf.y) * cp.y + sigf(vi.y) * tanh_fast(vg.y);
            cstA[p] = pack2(c0, c1);
            hA[0][p] = sigf(vo.x) * tanh_fast(c0);
            hA[1][p] = sigf(vo.y) * tanh_fast(c1);

            vi = unpack2(acc[1][0][p]);
            vf = unpack2(acc[1][1][p]);
            vo = unpack2(acc[1][2][p]);
            vg = unpack2(acc[1][3][p]);
            cp = unpack2(cstB[p]);
            c0 = sigf(vf.x) * cp.x + sigf(vi.x) * tanh_fast(vg.x);
            c1 = sigf(vf.y) * cp.y + sigf(vi.y) * tanh_fast(vg.y);
            cstB[p] = pack2(c0, c1);
            hB[0][p] = sigf(vo.x) * tanh_fast(c0);
            hB[1][p] = sigf(vo.y) * tanh_fast(c1);
        }

        __syncthreads();   // all conv reads of in_all done
        *reinterpret_cast<float4*>(inA + (3 + 2*hp) * 16 + r * 4) =
            make_float4(hA[0][0], hA[0][1], hA[0][2], hA[0][3]);
        *reinterpret_cast<float4*>(inA + (4 + 2*hp) * 16 + r * 4) =
            make_float4(hA[1][0], hA[1][1], hA[1][2], hA[1][3]);
        *reinterpret_cast<float4*>(inB + (3 + 2*hp) * 16 + r * 4) =
            make_float4(hB[0][0], hB[0][1], hB[0][2], hB[0][3]);
        *reinterpret_cast<float4*>(inB + (4 + 2*hp) * 16 + r * 4) =
            make_float4(hB[1][0], hB[1][1], hB[1][2], hB[1][3]);

        if (t < 11) {
            if (tid < NB * 12) {
                int bb = tid / 12, q = tid - bb * 12;
                int gb = b0 + bb;
                if (gb < B)
                    *reinterpret_cast<float4*>(in_all + bb * INS + q * 4) =
                        *reinterpret_cast<const float4*>(x + (size_t)gb * 576 + (t+1) * 48 + q * 4);
            }
        }
        __syncthreads();
    }

    // ------------------------------ decoder ------------------------------
    // 32 threads per batch; scratch z1/z2 reuse the dead conv-weight region.
    const int db   = tid >> 5;        // batch 0..15
    const int dtib = tid & 31;
    const int gb   = b0 + db;
    const bool dv  = (gb < B);
    const int gld  = dv ? gb : 0;

    // hour embedding -> hf_s[db][32]
    {
        float hv  = hour[gld];
        float a = he_b2[dtib];
        #pragma unroll
        for (int k2 = 0; k2 < 16; ++k2) {
            float tt = fmaxf(hv * he_w1[k2] + he_b1[k2], 0.0f);
            a += tt * he_w2[k2 * 32 + dtib];
        }
        hf_s[db * 32 + dtib] = a;
    }
    __syncthreads();

    // L1: 544 -> 256, 8 outputs/thread
    float a1[8];
    {
        const int j0 = dtib * 8;
        #pragma unroll
        for (int q = 0; q < 8; q++) a1[q] = d_b1[j0 + q];
        const float* zz = in_all + db * INS + 48;   // spatial 512
        #pragma unroll 2
        for (int i = 0; i < 512; ++i) {
            float zi = zz[i];
            float4 wa = *reinterpret_cast<const float4*>(d_w1 + i * 256 + j0);
            float4 wb = *reinterpret_cast<const float4*>(d_w1 + i * 256 + j0 + 4);
            a1[0] += zi * wa.x; a1[1] += zi * wa.y; a1[2] += zi * wa.z; a1[3] += zi * wa.w;
            a1[4] += zi * wb.x; a1[5] += zi * wb.y; a1[6] += zi * wb.z; a1[7] += zi * wb.w;
        }
        const float* hz = hf_s + db * 32;
        #pragma unroll 2
        for (int i = 0; i < 32; ++i) {
            float zi = hz[i];
            float4 wa = *reinterpret_cast<const float4*>(d_w1 + (512 + i) * 256 + j0);
            float4 wb = *reinterpret_cast<const float4*>(d_w1 + (512 + i) * 256 + j0 + 4);
            a1[0] += zi * wa.x; a1[1] += zi * wa.y; a1[2] += zi * wa.z; a1[3] += zi * wa.w;
            a1[4] += zi * wb.x; a1[5] += zi * wb.y; a1[6] += zi * wb.z; a1[7] += zi * wb.w;
        }
    }
    float* z1 = w_s;           // [16][256]
    float* z2 = w_s + 4096;    // [16][128]
    __syncthreads();           // weight region now safe to overwrite
    {
        const int j0 = dtib * 8;
        *reinterpret_cast<float4*>(z1 + db * 256 + j0) =
            make_float4(fmaxf(a1[0],0.f), fmaxf(a1[1],0.f), fmaxf(a1[2],0.f), fmaxf(a1[3],0.f));
        *reinterpret_cast<float4*>(z1 + db * 256 + j0 + 4) =
            make_float4(fmaxf(a1[4],0.f), fmaxf(a1[5],0.f), fmaxf(a1[6],0.f), fmaxf(a1[7],0.f));
    }
    __syncthreads();

    // L2: 256 -> 128, 4 outputs/thread
    {
        const int j0 = dtib * 4;
        float a2[4];
        #pragma unroll
        for (int q = 0; q < 4; q++) a2[q] = d_b2[j0 + q];
        const float* zzz = z1 + db * 256;
        #pragma unroll 2
        for (int i = 0; i < 256; ++i) {
            float zi = zzz[i];
            float4 w = *reinterpret_cast<const float4*>(d_w2 + i * 128 + j0);
            a2[0] += zi * w.x; a2[1] += zi * w.y; a2[2] += zi * w.z; a2[3] += zi * w.w;
        }
        *reinterpret_cast<float4*>(z2 + db * 128 + j0) =
            make_float4(fmaxf(a2[0],0.f), fmaxf(a2[1],0.f), fmaxf(a2[2],0.f), fmaxf(a2[3],0.f));
    }
    __syncthreads();

    // L3: 128 -> 30 + sigmoid
    if (dtib < 30 && dv) {
        float a3 = d_b3[dtib];
        const float* zzz = z2 + db * 128;
        #pragma unroll 4
        for (int i = 0; i < 128; ++i)
            a3 += zzz[i] * d_w3[i * 30 + dtib];
        out[(size_t)gb * 30 + dtib] = sigf(a3);
    }
}

extern "C" void kernel_launch(void* const* d_in, const int* in_sizes, int n_in,
                              void* d_out, int out_size)
{
    const float* x      = (const float*)d_in[0];
    const float* hour   = (const float*)d_in[1];
    const float* conv_w = (const float*)d_in[2];
    const float* conv_b = (const float*)d_in[3];
    const float* he_w1  = (const float*)d_in[4];
    const float* he_b1  = (const float*)d_in[5];
    const float* he_w2  = (const float*)d_in[6];
    const float* he_b2  = (const float*)d_in[7];
    const float* d_w1   = (const float*)d_in[8];
    const float* d_b1   = (const float*)d_in[9];
    const float* d_w2   = (const float*)d_in[10];
    const float* d_b2   = (const float*)d_in[11];
    const float* d_w3   = (const float*)d_in[12];
    const float* d_b3   = (const float*)d_in[13];

    const int B    = in_sizes[0] / 576;
    const int grid = (B + NB - 1) / NB;
    const size_t sm = (size_t)(WCNT + 128 + NB * INS + NB * 32) * sizeof(float); // 199,680 B

    cudaFuncSetAttribute(wq_fused_kernel,
                         cudaFuncAttributeMaxDynamicSharedMemorySize, (int)sm);

    wq_fused_kernel<<<grid, NTHR, sm>>>(x, hour, conv_w, conv_b,
                                        he_w1, he_b1, he_w2, he_b2,
                                        d_w1, d_b1, d_w2, d_b2, d_w3, d_b3,
                                        (float*)d_out, B);
}